// round 13
// baseline (speedup 1.0000x reference)
#include <cuda_runtime.h>

// ---------------------------------------------------------------------------
// Masked multi-level MSE loss (B=16, C=256, T=128, S in {80,40,20}):
//   L = mean_l [ sum((M_l * (p_l - t_l))^2) / (C * sum(M_l)) ]
//
// Single fused kernel == R6 champion, with 4-way oversubscription:
// 2368 blocks (4 waves at 4 blocks/SM). Contiguous equal unit ranges per
// block; the HW CTA scheduler backfills freed slots, absorbing the
// mask-density straggler tail that limited the one-wave version.
// SMEM box table (counting-sorted by batch); unit = one spatial float4
// position x CPU channels (CPU=16/4/4), 4-cell mask computed inline once per
// unit; quad4 inner loop = 8 independent LDG.128; skip at unit granularity.
// Counts on chunk==0 units. Last block finalizes (self-reset ticket).
// ---------------------------------------------------------------------------

#define NB 16
#define NT 128
#define NC 256
#define GRID_BLOCKS 2368
#define BT 256

__device__ float g_pa[3][GRID_BLOCKS];
__device__ int   g_pc[3][GRID_BLOCKS];
__device__ unsigned g_ticket = 0;

struct BoxTab {
    short4 box[3][NT];   // per level, sorted by batch: x=xl, y=xr, z=yt, w=yd
    int off[NB + 1];
    int cnt[NB];
};

// ---------------------------------------------------------------------------
__device__ __forceinline__ float block_sum_f(float v, float* sm) {
#pragma unroll
    for (int o = 16; o; o >>= 1) v += __shfl_down_sync(0xffffffffu, v, o);
    const int lane = threadIdx.x & 31, warp = threadIdx.x >> 5;
    if (lane == 0) sm[warp] = v;
    __syncthreads();
    v = (threadIdx.x < (BT / 32)) ? sm[threadIdx.x] : 0.f;
    if (warp == 0) {
#pragma unroll
        for (int o = 16; o; o >>= 1) v += __shfl_down_sync(0xffffffffu, v, o);
    }
    __syncthreads();
    return v;
}

__device__ __forceinline__ int block_sum_i(int v, int* sm) {
#pragma unroll
    for (int o = 16; o; o >>= 1) v += __shfl_down_sync(0xffffffffu, v, o);
    const int lane = threadIdx.x & 31, warp = threadIdx.x >> 5;
    if (lane == 0) sm[warp] = v;
    __syncthreads();
    v = (threadIdx.x < (BT / 32)) ? sm[threadIdx.x] : 0;
    if (warp == 0) {
#pragma unroll
        for (int o = 16; o; o >>= 1) v += __shfl_down_sync(0xffffffffu, v, o);
    }
    __syncthreads();
    return v;
}

// ---------------------------------------------------------------------------
// Process 4 f4 (one spatial f4 across 4 consecutive channels).
__device__ __forceinline__ void quad4(const float4* __restrict__ p,
                                      const float4* __restrict__ q,
                                      unsigned idx, unsigned CH4,
                                      float fm0, float fm1, float fm2, float fm3,
                                      float& acc0, float& acc1) {
    const float4 a0 = __ldg(p + idx);
    const float4 a1 = __ldg(p + idx + CH4);
    const float4 a2 = __ldg(p + idx + 2u * CH4);
    const float4 a3 = __ldg(p + idx + 3u * CH4);
    const float4 c0 = __ldg(q + idx);
    const float4 c1 = __ldg(q + idx + CH4);
    const float4 c2 = __ldg(q + idx + 2u * CH4);
    const float4 c3 = __ldg(q + idx + 3u * CH4);
    float d, e;
    d = a0.x - c0.x; e = fm0 * d; acc0 = fmaf(e, d, acc0);
    d = a0.y - c0.y; e = fm1 * d; acc1 = fmaf(e, d, acc1);
    d = a0.z - c0.z; e = fm2 * d; acc0 = fmaf(e, d, acc0);
    d = a0.w - c0.w; e = fm3 * d; acc1 = fmaf(e, d, acc1);
    d = a1.x - c1.x; e = fm0 * d; acc0 = fmaf(e, d, acc0);
    d = a1.y - c1.y; e = fm1 * d; acc1 = fmaf(e, d, acc1);
    d = a1.z - c1.z; e = fm2 * d; acc0 = fmaf(e, d, acc0);
    d = a1.w - c1.w; e = fm3 * d; acc1 = fmaf(e, d, acc1);
    d = a2.x - c2.x; e = fm0 * d; acc0 = fmaf(e, d, acc0);
    d = a2.y - c2.y; e = fm1 * d; acc1 = fmaf(e, d, acc1);
    d = a2.z - c2.z; e = fm2 * d; acc0 = fmaf(e, d, acc0);
    d = a2.w - c2.w; e = fm3 * d; acc1 = fmaf(e, d, acc1);
    d = a3.x - c3.x; e = fm0 * d; acc0 = fmaf(e, d, acc0);
    d = a3.y - c3.y; e = fm1 * d; acc1 = fmaf(e, d, acc1);
    d = a3.z - c3.z; e = fm2 * d; acc0 = fmaf(e, d, acc0);
    d = a3.w - c3.w; e = fm3 * d; acc1 = fmaf(e, d, acc1);
}

// ---------------------------------------------------------------------------
// Stream one level. Unit = one spatial f4 position x CPU channels.
template <int S, int CPU>
__device__ __forceinline__ void level_sum(const float4* __restrict__ p,
                                          const float4* __restrict__ q,
                                          const BoxTab* tb, int lvl,
                                          float& acc_out, int& cnt_out) {
    constexpr unsigned S4   = (unsigned)S / 4;
    constexpr unsigned CH4  = (unsigned)S * S4;        // f4 per channel image
    constexpr unsigned POS  = (unsigned)NB * CH4;      // spatial f4 positions
    constexpr unsigned U    = POS * ((unsigned)NC / (unsigned)CPU);

    const unsigned lo = (unsigned)((unsigned long long)blockIdx.x * U / GRID_BLOCKS);
    const unsigned hi = (unsigned)((unsigned long long)(blockIdx.x + 1) * U / GRID_BLOCKS);

    const short4* __restrict__ boxes = tb->box[lvl];
    float acc0 = 0.f, acc1 = 0.f;
    int cnt = 0;

#pragma unroll 1
    for (unsigned u = lo + threadIdx.x; u < hi; u += BT) {
        const unsigned chunk = u / POS;
        const unsigned pos   = u - chunk * POS;
        const unsigned b     = pos / CH4;
        const unsigned posr  = pos - b * CH4;
        const int y  = (int)(posr / S4);
        const int x0 = 4 * (int)(posr - (unsigned)y * S4);

        // inline 4-cell mask from the box table
        int m = 0;
        const int j1 = tb->off[b + 1];
#pragma unroll 1
        for (int j = tb->off[b]; j < j1; j++) {
            const short4 bx = boxes[j];
            if (y >= (int)bx.z && y <= (int)bx.w) {
                int l = (int)bx.x - x0; l = l < 0 ? 0 : l;
                int r = (int)bx.y - x0; r = r > 3 ? 3 : r;
                if (l <= r) m |= (0xF << l) & (0xF >> (3 - r));
            }
        }
        if (chunk == 0) cnt += __popc(m);
        if (m == 0) continue;

        const float fm0 = __uint_as_float(( m       & 1) * 0x3F800000u);
        const float fm1 = __uint_as_float(((m >> 1) & 1) * 0x3F800000u);
        const float fm2 = __uint_as_float(((m >> 2) & 1) * 0x3F800000u);
        const float fm3 = __uint_as_float(((m >> 3) & 1) * 0x3F800000u);

        unsigned idx = b * ((unsigned)NC * CH4) + chunk * ((unsigned)CPU * CH4) + posr;

#pragma unroll 1
        for (int cc = 0; cc < CPU; cc += 4) {
            quad4(p, q, idx, CH4, fm0, fm1, fm2, fm3, acc0, acc1);
            idx += 4u * CH4;
        }
    }
    acc_out = acc0 + acc1;
    cnt_out = cnt;
}

// ---------------------------------------------------------------------------
__global__ void __launch_bounds__(BT, 4)
fused_kernel(const float4* __restrict__ p0, const float4* __restrict__ t0,
             const float4* __restrict__ p1, const float4* __restrict__ t1,
             const float4* __restrict__ p2, const float4* __restrict__ t2,
             const float* __restrict__ bboxes,
             const int* __restrict__ batch_idx,
             float* __restrict__ out) {
    __shared__ BoxTab tb;
    __shared__ float smf[32];
    __shared__ int smi[32];

    // ---- build box table (counting sort by batch) ----
    if (threadIdx.x < NB) tb.cnt[threadIdx.x] = 0;
    __syncthreads();
    int myb = 0, myrank = 0;
    float4 bb;
    if (threadIdx.x < NT) {
        myb = batch_idx[threadIdx.x];
        bb = ((const float4*)bboxes)[threadIdx.x];
        myrank = atomicAdd(&tb.cnt[myb], 1);
    }
    __syncthreads();
    if (threadIdx.x == 0) {
        int s = 0;
        tb.off[0] = 0;
#pragma unroll
        for (int i = 0; i < NB; i++) { s += tb.cnt[i]; tb.off[i + 1] = s; }
    }
    __syncthreads();
    if (threadIdx.x < NT) {
        const int g = tb.off[myb] + myrank;
#pragma unroll
        for (int lvl = 0; lvl < 3; lvl++) {
            const int S = (lvl == 0) ? 80 : (lvl == 1) ? 40 : 20;
            const float fS = (float)S;
            int xc = (int)floorf(bb.x * fS);
            int yc = (int)floorf(bb.y * fS);
            int w  = (int)floorf(bb.z * fS);
            int h  = (int)floorf(bb.w * fS);
            short xl = (short)max(xc - w / 2, 0);
            short yt = (short)max(yc - h / 2, 0);
            short xr = (short)min(xc + w / 2, S - 1);
            short yd = (short)min(yc + h / 2, S - 1);
            tb.box[lvl][g] = make_short4(xl, xr, yt, yd);
        }
    }
    __syncthreads();

    // ---- stream all three levels ----
    float a0, a1, a2;
    int c0, c1, c2;
    level_sum<80, 16>(p0, t0, &tb, 0, a0, c0);
    level_sum<40, 4>(p1, t1, &tb, 1, a1, c1);
    level_sum<20, 4>(p2, t2, &tb, 2, a2, c2);

    a0 = block_sum_f(a0, smf);
    a1 = block_sum_f(a1, smf);
    a2 = block_sum_f(a2, smf);
    c0 = block_sum_i(c0, smi);
    c1 = block_sum_i(c1, smi);
    c2 = block_sum_i(c2, smi);

    __shared__ bool s_last;
    if (threadIdx.x == 0) {
        g_pa[0][blockIdx.x] = a0;
        g_pa[1][blockIdx.x] = a1;
        g_pa[2][blockIdx.x] = a2;
        g_pc[0][blockIdx.x] = c0;
        g_pc[1][blockIdx.x] = c1;
        g_pc[2][blockIdx.x] = c2;
        __threadfence();
        unsigned n = atomicAdd(&g_ticket, 1u);
        s_last = (n == GRID_BLOCKS - 1);
    }
    __syncthreads();
    if (!s_last) return;

    // ---- finalize (last block only) ----
    float fa0 = 0.f, fa1 = 0.f, fa2 = 0.f;
    int fc0 = 0, fc1 = 0, fc2 = 0;
    for (int i = threadIdx.x; i < GRID_BLOCKS; i += BT) {
        fa0 += g_pa[0][i]; fa1 += g_pa[1][i]; fa2 += g_pa[2][i];
        fc0 += g_pc[0][i]; fc1 += g_pc[1][i]; fc2 += g_pc[2][i];
    }
    fa0 = block_sum_f(fa0, smf);
    fa1 = block_sum_f(fa1, smf);
    fa2 = block_sum_f(fa2, smf);
    fc0 = block_sum_i(fc0, smi);
    fc1 = block_sum_i(fc1, smi);
    fc2 = block_sum_i(fc2, smi);

    if (threadIdx.x == 0) {
        double L = (double)fa0 / (256.0 * (double)fc0) +
                   (double)fa1 / (256.0 * (double)fc1) +
                   (double)fa2 / (256.0 * (double)fc2);
        out[0] = (float)(L / 3.0);
        __threadfence();
        g_ticket = 0;   // restore for next graph replay
    }
}

// ---------------------------------------------------------------------------
extern "C" void kernel_launch(void* const* d_in, const int* in_sizes, int n_in,
                              void* d_out, int out_size) {
    // input order: pred0, true0, pred1, true1, pred2, true2, bboxes, batch_idx, cls
    const float4* p0 = (const float4*)d_in[0];
    const float4* t0 = (const float4*)d_in[1];
    const float4* p1 = (const float4*)d_in[2];
    const float4* t1 = (const float4*)d_in[3];
    const float4* p2 = (const float4*)d_in[4];
    const float4* t2 = (const float4*)d_in[5];
    const float* bboxes = (const float*)d_in[6];
    const int* batch_idx = (const int*)d_in[7];

    fused_kernel<<<GRID_BLOCKS, BT>>>(p0, t0, p1, t1, p2, t2,
                                      bboxes, batch_idx, (float*)d_out);
}

// round 14
// speedup vs baseline: 1.2648x; 1.2648x over previous
#include <cuda_runtime.h>

// ---------------------------------------------------------------------------
// Masked multi-level MSE loss (B=16, C=256, T=128, S in {80,40,20}):
//   L = mean_l [ sum((M_l * (p_l - t_l))^2) / (C * sum(M_l)) ]
//
// Single fused kernel, one wave of 592 blocks (148 SMs x 4, 64-reg budget).
// Each block: builds an SMEM box table (128 boxes counting-sorted by batch,
// per-level integer coords), then streams its balanced contiguous unit range
// per level. A unit = one spatial float4 position x CPU channels; its 4-cell
// mask is computed INLINE from the box table (no mask arrays, no mask loads).
// Inner loop: 8 independent LDG.128 per step. Positive-cell count taken on
// chunk==0 units (each position counted exactly once chip-wide).
// Last block finalizes into d_out (self-resetting ticket).
// ---------------------------------------------------------------------------

#define NB 16
#define NT 128
#define NC 256
#define GRID_BLOCKS 592
#define BT 256

__device__ float g_pa[3][GRID_BLOCKS];
__device__ int   g_pc[3][GRID_BLOCKS];
__device__ unsigned g_ticket = 0;

struct BoxTab {
    short4 box[3][NT];   // per level, sorted by batch: x=xl, y=xr, z=yt, w=yd
    int off[NB + 1];     // batch -> [off[b], off[b+1]) in box[]
    int cnt[NB];
};

// ---------------------------------------------------------------------------
__device__ __forceinline__ float block_sum_f(float v, float* sm) {
#pragma unroll
    for (int o = 16; o; o >>= 1) v += __shfl_down_sync(0xffffffffu, v, o);
    const int lane = threadIdx.x & 31, warp = threadIdx.x >> 5;
    if (lane == 0) sm[warp] = v;
    __syncthreads();
    v = (threadIdx.x < (BT / 32)) ? sm[threadIdx.x] : 0.f;
    if (warp == 0) {
#pragma unroll
        for (int o = 16; o; o >>= 1) v += __shfl_down_sync(0xffffffffu, v, o);
    }
    __syncthreads();
    return v;
}

__device__ __forceinline__ int block_sum_i(int v, int* sm) {
#pragma unroll
    for (int o = 16; o; o >>= 1) v += __shfl_down_sync(0xffffffffu, v, o);
    const int lane = threadIdx.x & 31, warp = threadIdx.x >> 5;
    if (lane == 0) sm[warp] = v;
    __syncthreads();
    v = (threadIdx.x < (BT / 32)) ? sm[threadIdx.x] : 0;
    if (warp == 0) {
#pragma unroll
        for (int o = 16; o; o >>= 1) v += __shfl_down_sync(0xffffffffu, v, o);
    }
    __syncthreads();
    return v;
}

// ---------------------------------------------------------------------------
// Stream one level. Unit = spatial f4 position x CPU channels (CPU % 4 == 0).
template <int S, int CPU>
__device__ __forceinline__ void level_sum(const float4* __restrict__ p,
                                          const float4* __restrict__ q,
                                          const BoxTab* tb, int lvl,
                                          float& acc_out, int& cnt_out) {
    constexpr unsigned S4   = (unsigned)S / 4;
    constexpr unsigned CH4  = (unsigned)S * S4;        // f4 per channel image
    constexpr unsigned POS  = (unsigned)NB * CH4;      // spatial f4 positions
    constexpr unsigned U    = POS * ((unsigned)NC / (unsigned)CPU);

    const unsigned lo = (unsigned)((unsigned long long)blockIdx.x * U / GRID_BLOCKS);
    const unsigned hi = (unsigned)((unsigned long long)(blockIdx.x + 1) * U / GRID_BLOCKS);

    const short4* __restrict__ boxes = tb->box[lvl];
    float acc0 = 0.f, acc1 = 0.f;
    int cnt = 0;

#pragma unroll 1
    for (unsigned u = lo + threadIdx.x; u < hi; u += BT) {
        const unsigned chunk = u / POS;
        const unsigned pos   = u - chunk * POS;
        const unsigned b     = pos / CH4;
        const unsigned posr  = pos - b * CH4;
        const int y  = (int)(posr / S4);
        const int x0 = 4 * (int)(posr - (unsigned)y * S4);

        // inline 4-cell mask from the box table
        int m = 0;
        const int j1 = tb->off[b + 1];
#pragma unroll 1
        for (int j = tb->off[b]; j < j1; j++) {
            const short4 bx = boxes[j];
            if (y >= (int)bx.z && y <= (int)bx.w) {
                int l = (int)bx.x - x0; l = l < 0 ? 0 : l;
                int r = (int)bx.y - x0; r = r > 3 ? 3 : r;
                if (l <= r) m |= (0xF << l) & (0xF >> (3 - r));
            }
        }
        if (chunk == 0) cnt += __popc(m);
        if (m == 0) continue;

        const float fm0 = __uint_as_float(( m       & 1) * 0x3F800000u);
        const float fm1 = __uint_as_float(((m >> 1) & 1) * 0x3F800000u);
        const float fm2 = __uint_as_float(((m >> 2) & 1) * 0x3F800000u);
        const float fm3 = __uint_as_float(((m >> 3) & 1) * 0x3F800000u);

        unsigned idx = b * ((unsigned)NC * CH4) + chunk * ((unsigned)CPU * CH4) + posr;
#pragma unroll 1
        for (int cc = 0; cc < CPU; cc += 4) {
            const float4 a0 = __ldg(p + idx);
            const float4 a1 = __ldg(p + idx + CH4);
            const float4 a2 = __ldg(p + idx + 2u * CH4);
            const float4 a3 = __ldg(p + idx + 3u * CH4);
            const float4 c0 = __ldg(q + idx);
            const float4 c1 = __ldg(q + idx + CH4);
            const float4 c2 = __ldg(q + idx + 2u * CH4);
            const float4 c3 = __ldg(q + idx + 3u * CH4);
            float d, e;
            d = a0.x - c0.x; e = fm0 * d; acc0 = fmaf(e, d, acc0);
            d = a0.y - c0.y; e = fm1 * d; acc1 = fmaf(e, d, acc1);
            d = a0.z - c0.z; e = fm2 * d; acc0 = fmaf(e, d, acc0);
            d = a0.w - c0.w; e = fm3 * d; acc1 = fmaf(e, d, acc1);
            d = a1.x - c1.x; e = fm0 * d; acc0 = fmaf(e, d, acc0);
            d = a1.y - c1.y; e = fm1 * d; acc1 = fmaf(e, d, acc1);
            d = a1.z - c1.z; e = fm2 * d; acc0 = fmaf(e, d, acc0);
            d = a1.w - c1.w; e = fm3 * d; acc1 = fmaf(e, d, acc1);
            d = a2.x - c2.x; e = fm0 * d; acc0 = fmaf(e, d, acc0);
            d = a2.y - c2.y; e = fm1 * d; acc1 = fmaf(e, d, acc1);
            d = a2.z - c2.z; e = fm2 * d; acc0 = fmaf(e, d, acc0);
            d = a2.w - c2.w; e = fm3 * d; acc1 = fmaf(e, d, acc1);
            d = a3.x - c3.x; e = fm0 * d; acc0 = fmaf(e, d, acc0);
            d = a3.y - c3.y; e = fm1 * d; acc1 = fmaf(e, d, acc1);
            d = a3.z - c3.z; e = fm2 * d; acc0 = fmaf(e, d, acc0);
            d = a3.w - c3.w; e = fm3 * d; acc1 = fmaf(e, d, acc1);
            idx += 4u * CH4;
        }
    }
    acc_out = acc0 + acc1;
    cnt_out = cnt;
}

// ---------------------------------------------------------------------------
__global__ void __launch_bounds__(BT, 4)
fused_kernel(const float4* __restrict__ p0, const float4* __restrict__ t0,
             const float4* __restrict__ p1, const float4* __restrict__ t1,
             const float4* __restrict__ p2, const float4* __restrict__ t2,
             const float* __restrict__ bboxes,
             const int* __restrict__ batch_idx,
             float* __restrict__ out) {
    __shared__ BoxTab tb;
    __shared__ float smf[32];
    __shared__ int smi[32];

    // ---- build box table (counting sort by batch; order within batch free) --
    if (threadIdx.x < NB) tb.cnt[threadIdx.x] = 0;
    __syncthreads();
    int myb = 0, myrank = 0;
    float4 bb;
    if (threadIdx.x < NT) {
        myb = batch_idx[threadIdx.x];
        bb = ((const float4*)bboxes)[threadIdx.x];
        myrank = atomicAdd(&tb.cnt[myb], 1);
    }
    __syncthreads();
    if (threadIdx.x == 0) {
        int s = 0;
        tb.off[0] = 0;
#pragma unroll
        for (int i = 0; i < NB; i++) { s += tb.cnt[i]; tb.off[i + 1] = s; }
    }
    __syncthreads();
    if (threadIdx.x < NT) {
        const int g = tb.off[myb] + myrank;
#pragma unroll
        for (int lvl = 0; lvl < 3; lvl++) {
            const int S = (lvl == 0) ? 80 : (lvl == 1) ? 40 : 20;
            const float fS = (float)S;
            int xc = (int)floorf(bb.x * fS);
            int yc = (int)floorf(bb.y * fS);
            int w  = (int)floorf(bb.z * fS);
            int h  = (int)floorf(bb.w * fS);
            short xl = (short)max(xc - w / 2, 0);
            short yt = (short)max(yc - h / 2, 0);
            short xr = (short)min(xc + w / 2, S - 1);
            short yd = (short)min(yc + h / 2, S - 1);
            tb.box[lvl][g] = make_short4(xl, xr, yt, yd);
        }
    }
    __syncthreads();

    // ---- stream all three levels ----
    float a0, a1, a2;
    int c0, c1, c2;
    level_sum<80, 16>(p0, t0, &tb, 0, a0, c0);
    level_sum<40, 4>(p1, t1, &tb, 1, a1, c1);
    level_sum<20, 4>(p2, t2, &tb, 2, a2, c2);

    a0 = block_sum_f(a0, smf);
    a1 = block_sum_f(a1, smf);
    a2 = block_sum_f(a2, smf);
    c0 = block_sum_i(c0, smi);
    c1 = block_sum_i(c1, smi);
    c2 = block_sum_i(c2, smi);

    __shared__ bool s_last;
    if (threadIdx.x == 0) {
        g_pa[0][blockIdx.x] = a0;
        g_pa[1][blockIdx.x] = a1;
        g_pa[2][blockIdx.x] = a2;
        g_pc[0][blockIdx.x] = c0;
        g_pc[1][blockIdx.x] = c1;
        g_pc[2][blockIdx.x] = c2;
        __threadfence();
        unsigned n = atomicAdd(&g_ticket, 1u);
        s_last = (n == GRID_BLOCKS - 1);
    }
    __syncthreads();
    if (!s_last) return;

    // ---- finalize (last block only) ----
    float fa0 = 0.f, fa1 = 0.f, fa2 = 0.f;
    int fc0 = 0, fc1 = 0, fc2 = 0;
    for (int i = threadIdx.x; i < GRID_BLOCKS; i += BT) {
        fa0 += g_pa[0][i]; fa1 += g_pa[1][i]; fa2 += g_pa[2][i];
        fc0 += g_pc[0][i]; fc1 += g_pc[1][i]; fc2 += g_pc[2][i];
    }
    fa0 = block_sum_f(fa0, smf);
    fa1 = block_sum_f(fa1, smf);
    fa2 = block_sum_f(fa2, smf);
    fc0 = block_sum_i(fc0, smi);
    fc1 = block_sum_i(fc1, smi);
    fc2 = block_sum_i(fc2, smi);

    if (threadIdx.x == 0) {
        double L = (double)fa0 / (256.0 * (double)fc0) +
                   (double)fa1 / (256.0 * (double)fc1) +
                   (double)fa2 / (256.0 * (double)fc2);
        out[0] = (float)(L / 3.0);
        __threadfence();
        g_ticket = 0;   // restore for next graph replay
    }
}

// ---------------------------------------------------------------------------
extern "C" void kernel_launch(void* const* d_in, const int* in_sizes, int n_in,
                              void* d_out, int out_size) {
    // input order: pred0, true0, pred1, true1, pred2, true2, bboxes, batch_idx, cls
    const float4* p0 = (const float4*)d_in[0];
    const float4* t0 = (const float4*)d_in[1];
    const float4* p1 = (const float4*)d_in[2];
    const float4* t1 = (const float4*)d_in[3];
    const float4* p2 = (const float4*)d_in[4];
    const float4* t2 = (const float4*)d_in[5];
    const float* bboxes = (const float*)d_in[6];
    const int* batch_idx = (const int*)d_in[7];

    fused_kernel<<<GRID_BLOCKS, BT>>>(p0, t0, p1, t1, p2, t2,
                                      bboxes, batch_idx, (float*)d_out);
}